// round 3
// baseline (speedup 1.0000x reference)
#include <cuda_runtime.h>

// ---------------------------------------------------------------------------
// FeedBack LSTM: 48 warmup steps over x, then 24 autoregressive steps feeding
// pred = h@Wd + bd back as the next input.
//
// B=16384, T=48, F=4, UNITS=256 (z width 1024), OUT_STEPS=24.
//
// Round 3: fixed cross-block race on h. Every block's GEMM reads ALL unit
// columns of its h rows while sibling blocks (same rows, different units)
// write new h in the same launch -> double-buffer h (ping-pong per step).
// ---------------------------------------------------------------------------

namespace {
constexpr int BATCH = 16384;
constexpr int SEQ_T = 48;
constexpr int FDIM  = 4;
constexpr int NU    = 256;      // UNITS
constexpr int NOUT  = 24;       // OUT_STEPS
constexpr int Z4    = 4 * NU;   // 1024

constexpr int BM = 128;         // rows per block
constexpr int BU = 32;          // units per block (x4 gates = 128 z-cols)
constexpr int BK = 16;          // k tile
constexpr int THREADS = 256;
}

// scratch state (device globals: allocation-free per harness rules)
// h is double-buffered: step t reads buffer (t-1)&1, writes buffer t&1.
__device__ float g_h0[BATCH * NU];
__device__ float g_h1[BATCH * NU];
__device__ float g_c[BATCH * NU];
__device__ float g_pred[BATCH * FDIM];

// accurate activations (tanhf ~1-2 ulp) so recurrence error stays ~1e-5.
__device__ __forceinline__ float sigmoid_acc(float x) {
    return 0.5f * (1.0f + tanhf(0.5f * x));
}

// One LSTM timestep, fused GEMM + cell update.
// xt: [BATCH, FDIM] rows with stride xstride (floats).
__global__ void __launch_bounds__(THREADS, 2)
lstm_step_kernel(const float* __restrict__ xt, int xstride,
                 const float* __restrict__ Wx,     // [4, 1024]
                 const float* __restrict__ Wh,     // [256, 1024]
                 const float* __restrict__ bias,   // [1024]
                 const float* __restrict__ h_in,   // [B, 256] (prev step)
                 float* __restrict__ h_out,        // [B, 256] (this step)
                 int first)
{
    __shared__ float a_s[BK][BM];            // h tile, transposed: [k][row]
    __shared__ float w_s[BK][4][BU];         // Wh tile: [k][gate][unit]
    __shared__ float wx_s[FDIM][4][BU];      // Wx slice
    __shared__ float b_s[4][BU];             // bias slice

    const int tid   = threadIdx.x;
    const int tx    = tid & 15;              // unit group (2 units each)
    const int ty    = tid >> 4;              // row group (8 rows each)
    const int ubase = blockIdx.x * BU;
    const int rbase = blockIdx.y * BM;

    // preload Wx slice + bias slice
    for (int i = tid; i < FDIM * 4 * BU; i += THREADS) {
        int f = i >> 7;           // /128
        int g = (i >> 5) & 3;     // /32 %4
        int u = i & 31;
        wx_s[f][g][u] = Wx[f * Z4 + g * NU + ubase + u];
    }
    if (tid < 4 * BU) {
        int g = tid >> 5;
        int u = tid & 31;
        b_s[g][u] = bias[g * NU + ubase + u];
    }
    __syncthreads();

    float acc[8][2][4];
    #pragma unroll
    for (int m = 0; m < 8; m++)
        #pragma unroll
        for (int uu = 0; uu < 2; uu++)
            #pragma unroll
            for (int g = 0; g < 4; g++)
                acc[m][uu][g] = 0.0f;

    if (!first) {
        for (int k0 = 0; k0 < NU; k0 += BK) {
            // --- load h tile (transposed into a_s) ---
            {
                int j   = tid * 8;
                int row = j >> 4;        // tid/2
                int kk  = j & 15;        // 0 or 8
                const float4* src = reinterpret_cast<const float4*>(
                    &h_in[(rbase + row) * NU + k0 + kk]);
                float4 v0 = src[0];
                float4 v1 = src[1];
                a_s[kk + 0][row] = v0.x; a_s[kk + 1][row] = v0.y;
                a_s[kk + 2][row] = v0.z; a_s[kk + 3][row] = v0.w;
                a_s[kk + 4][row] = v1.x; a_s[kk + 5][row] = v1.y;
                a_s[kk + 6][row] = v1.z; a_s[kk + 7][row] = v1.w;
            }
            // --- load Wh tile ---
            {
                int j   = tid * 8;
                int k   = j >> 7;        // /128
                int rem = j & 127;
                int g   = rem >> 5;
                int u   = rem & 31;      // multiple of 8
                const float4* src = reinterpret_cast<const float4*>(
                    &Wh[(k0 + k) * Z4 + g * NU + ubase + u]);
                float4 v0 = src[0];
                float4 v1 = src[1];
                *reinterpret_cast<float4*>(&w_s[k][g][u])     = v0;
                *reinterpret_cast<float4*>(&w_s[k][g][u + 4]) = v1;
            }
            __syncthreads();

            #pragma unroll
            for (int k = 0; k < BK; k++) {
                float4 av0 = *reinterpret_cast<const float4*>(&a_s[k][ty * 8]);
                float4 av1 = *reinterpret_cast<const float4*>(&a_s[k][ty * 8 + 4]);
                float a[8] = {av0.x, av0.y, av0.z, av0.w,
                              av1.x, av1.y, av1.z, av1.w};
                float w[4][2];
                #pragma unroll
                for (int g = 0; g < 4; g++) {
                    float2 wv = *reinterpret_cast<const float2*>(&w_s[k][g][tx * 2]);
                    w[g][0] = wv.x; w[g][1] = wv.y;
                }
                #pragma unroll
                for (int m = 0; m < 8; m++)
                    #pragma unroll
                    for (int uu = 0; uu < 2; uu++)
                        #pragma unroll
                        for (int g = 0; g < 4; g++)
                            acc[m][uu][g] = fmaf(a[m], w[g][uu], acc[m][uu][g]);
            }
            __syncthreads();
        }
    }

    // --- epilogue: + x@Wx + b, LSTM cell update, write h,c ---
    #pragma unroll
    for (int m = 0; m < 8; m++) {
        const int row = rbase + ty * 8 + m;
        float4 xv = *reinterpret_cast<const float4*>(&xt[(long)row * xstride]);
        const float xf[4] = {xv.x, xv.y, xv.z, xv.w};

        const int uoff = row * NU + ubase + tx * 2;

        float2 cold;
        if (!first) cold = *reinterpret_cast<const float2*>(&g_c[uoff]);
        else        cold = make_float2(0.0f, 0.0f);
        const float coldv[2] = {cold.x, cold.y};

        float hnew[2], cnew[2];
        #pragma unroll
        for (int uu = 0; uu < 2; uu++) {
            const int u = tx * 2 + uu;
            float z[4];
            #pragma unroll
            for (int g = 0; g < 4; g++) {
                float zz = acc[m][uu][g] + b_s[g][u];
                #pragma unroll
                for (int f = 0; f < 4; f++)
                    zz = fmaf(xf[f], wx_s[f][g][u], zz);
                z[g] = zz;
            }
            const float ig = sigmoid_acc(z[0]);
            const float fg = sigmoid_acc(z[1]);
            const float gg = tanhf(z[2]);
            const float og = sigmoid_acc(z[3]);
            const float cn = fg * coldv[uu] + ig * gg;
            cnew[uu] = cn;
            hnew[uu] = og * tanhf(cn);
        }
        *reinterpret_cast<float2*>(&g_c[uoff]) = make_float2(cnew[0], cnew[1]);
        *reinterpret_cast<float2*>(&h_out[uoff]) = make_float2(hnew[0], hnew[1]);
    }
}

// pred = h @ Wd + bd ; writes output slice (stride ostride floats) and g_pred.
__global__ void pred_kernel(const float* __restrict__ h,    // [B, 256]
                            const float* __restrict__ Wd,   // [256, 4]
                            const float* __restrict__ bd,   // [4]
                            float* __restrict__ out, int ostride,
                            float* __restrict__ pred)
{
    const int gwarp = (blockIdx.x * blockDim.x + threadIdx.x) >> 5;
    const int lane  = threadIdx.x & 31;
    if (gwarp >= BATCH) return;

    const float* hrow = h + gwarp * NU;
    float a0 = 0.f, a1 = 0.f, a2 = 0.f, a3 = 0.f;
    #pragma unroll
    for (int k = lane; k < NU; k += 32) {
        float hv = hrow[k];
        float4 wv = *reinterpret_cast<const float4*>(&Wd[k * 4]);
        a0 = fmaf(hv, wv.x, a0);
        a1 = fmaf(hv, wv.y, a1);
        a2 = fmaf(hv, wv.z, a2);
        a3 = fmaf(hv, wv.w, a3);
    }
    #pragma unroll
    for (int off = 16; off > 0; off >>= 1) {
        a0 += __shfl_down_sync(0xffffffffu, a0, off);
        a1 += __shfl_down_sync(0xffffffffu, a1, off);
        a2 += __shfl_down_sync(0xffffffffu, a2, off);
        a3 += __shfl_down_sync(0xffffffffu, a3, off);
    }
    if (lane == 0) {
        float4 r = make_float4(a0 + bd[0], a1 + bd[1], a2 + bd[2], a3 + bd[3]);
        *reinterpret_cast<float4*>(&out[(long)gwarp * ostride]) = r;
        *reinterpret_cast<float4*>(&pred[gwarp * 4]) = r;
    }
}

extern "C" void kernel_launch(void* const* d_in, const int* in_sizes, int n_in,
                              void* d_out, int out_size)
{
    const float* x  = (const float*)d_in[0];  // [B, T, F]
    const float* Wx = (const float*)d_in[1];  // [F, 4U]
    const float* Wh = (const float*)d_in[2];  // [U, 4U]
    const float* b  = (const float*)d_in[3];  // [4U]
    const float* Wd = (const float*)d_in[4];  // [U, F]
    const float* bd = (const float*)d_in[5];  // [F]
    float* out = (float*)d_out;               // [B, OUT_STEPS, F]

    float* pred_ptr = nullptr;
    float* h0 = nullptr;
    float* h1 = nullptr;
    cudaGetSymbolAddress((void**)&pred_ptr, g_pred);
    cudaGetSymbolAddress((void**)&h0, g_h0);
    cudaGetSymbolAddress((void**)&h1, g_h1);

    const dim3 sgrid(NU / BU, BATCH / BM);    // (8, 128)
    const int pblocks = (BATCH * 32) / 256;   // warp per row

    float* hbuf[2] = {h0, h1};
    int step = 0;  // step t writes hbuf[t&1], reads hbuf[(t-1)&1]

    // warmup: 48 steps over the input window (first step skips GEMM, h=c=0)
    lstm_step_kernel<<<sgrid, THREADS>>>(x, SEQ_T * FDIM, Wx, Wh, b,
                                         hbuf[1], hbuf[0], 1);
    step = 1;
    for (int t = 1; t < SEQ_T; t++, step++)
        lstm_step_kernel<<<sgrid, THREADS>>>(x + t * FDIM, SEQ_T * FDIM, Wx, Wh, b,
                                             hbuf[(step - 1) & 1], hbuf[step & 1], 0);

    // pred0 (reads h written by step 47 = hbuf[47&1])
    pred_kernel<<<pblocks, 256>>>(hbuf[(step - 1) & 1], Wd, bd,
                                  out, NOUT * FDIM, pred_ptr);

    // autoregressive steps
    for (int s = 1; s < NOUT; s++, step++) {
        lstm_step_kernel<<<sgrid, THREADS>>>(pred_ptr, FDIM, Wx, Wh, b,
                                             hbuf[(step - 1) & 1], hbuf[step & 1], 0);
        pred_kernel<<<pblocks, 256>>>(hbuf[step & 1], Wd, bd,
                                      out + s * FDIM, NOUT * FDIM, pred_ptr);
    }
}

// round 5
// speedup vs baseline: 2.3307x; 2.3307x over previous
#include <cuda_runtime.h>
#include <cuda_bf16.h>
#include <cstdint>

// ---------------------------------------------------------------------------
// FeedBack LSTM via mma.sync bf16 (baseline PTX — harness targets sm_103,
// so tcgen05/'a'-gated features are unavailable).
// z = h@Wh (bf16 hi/lo split, 3 MMA terms, fp32 accum) + x@Wx + b, fused
// LSTM cell update in registers (gate-interleaved N permutation).
// B=16384, T=48, F=4, UNITS=256 (z width 1024), OUT_STEPS=24.
// ---------------------------------------------------------------------------

namespace {
constexpr int BATCH = 16384;
constexpr int SEQ_T = 48;
constexpr int FDIM  = 4;
constexpr int NU    = 256;
constexpr int NOUT  = 24;
constexpr int Z4    = 1024;

constexpr int THREADS = 256;        // 8 warps: 4 m-warps x 2 n-warps
constexpr int ROWB = 80;            // padded smem/gmem tile row (64B data+16B pad)
constexpr int TILE_B = 128 * ROWB;  // 10240 bytes per 128x32 tile
constexpr int TILE_E = TILE_B / 2;  // 5120 bf16 elems
constexpr int STAGE_B = 4 * TILE_B; // AH|AL|BH|BL = 40960
constexpr int SMEM_WX = 2 * STAGE_B;          // 81920
constexpr int SMEM_BIAS = SMEM_WX + 4*128*4;  // 83968
constexpr int SMEM_TOTAL = SMEM_BIAS + 512;   // 84480
}

// ---------------- device state (allocation-free) ----------------
// A = h as bf16 hi/lo, double-buffered, padded chunk layout:
// [buf][rt(128)][kc(8)] tiles of 128 rows x 80B (32 k elems + pad).
__device__ __align__(16) __nv_bfloat16 g_ah[2 * 128 * 8 * TILE_E];
__device__ __align__(16) __nv_bfloat16 g_al[2 * 128 * 8 * TILE_E];
// B = Wh permuted (gate-interleaved), padded chunk layout: [nt(8)][kc(8)] tiles.
__device__ __align__(16) __nv_bfloat16 g_bh[8 * 8 * TILE_E];
__device__ __align__(16) __nv_bfloat16 g_bl[8 * 8 * TILE_E];
// permuted Wx / b (fp32)
__device__ float g_wxp[FDIM * Z4];
__device__ float g_bp[Z4];
// fp32 state
__device__ float g_h[BATCH * NU];
__device__ float g_c[BATCH * NU];
__device__ float g_pred[BATCH * FDIM];

// ---------------- ptx helpers (all baseline PTX, no 'a' features) ----------
__device__ __forceinline__ void cp16(uint32_t dst, const void* src) {
    asm volatile("cp.async.cg.shared.global [%0], [%1], 16;"
                 :: "r"(dst), "l"(__cvta_generic_to_global(src)) : "memory");
}
__device__ __forceinline__ void ldsm4(uint32_t* r, uint32_t a) {
    asm volatile("ldmatrix.sync.aligned.m8n8.x4.shared.b16 {%0,%1,%2,%3}, [%4];"
                 : "=r"(r[0]), "=r"(r[1]), "=r"(r[2]), "=r"(r[3]) : "r"(a));
}
__device__ __forceinline__ void ldsm2(uint32_t* r, uint32_t a) {
    asm volatile("ldmatrix.sync.aligned.m8n8.x2.shared.b16 {%0,%1}, [%2];"
                 : "=r"(r[0]), "=r"(r[1]) : "r"(a));
}
__device__ __forceinline__ void mma16816(float* d, const uint32_t* a,
                                         const uint32_t* b) {
    asm volatile(
        "mma.sync.aligned.m16n8k16.row.col.f32.bf16.bf16.f32 "
        "{%0,%1,%2,%3}, {%4,%5,%6,%7}, {%8,%9}, {%0,%1,%2,%3};"
        : "+f"(d[0]), "+f"(d[1]), "+f"(d[2]), "+f"(d[3])
        : "r"(a[0]), "r"(a[1]), "r"(a[2]), "r"(a[3]), "r"(b[0]), "r"(b[1]));
}
__device__ __forceinline__ float sigmoid_acc(float x) {
    return 0.5f * (1.0f + tanhf(0.5f * x));
}

// ---------------- prep kernels ----------------
// Permutation: permuted col p -> nt=p>>7, loc=p&127; wn=loc>>6, g=(loc>>4)&3,
// ul=loc&15; unit u = nt*32 + wn*16 + ul; original col oc = g*256 + u.
__global__ void prep_weights(const float* __restrict__ Wh) {
    int idx = blockIdx.x * 256 + threadIdx.x;   // 262144 = 1024 p x 256 k
    int p = idx >> 8;
    int k = idx & 255;
    int nt = p >> 7, loc = p & 127;
    int wn = loc >> 6, g = (loc >> 4) & 3, ul = loc & 15;
    int u = nt * 32 + wn * 16 + ul;
    int oc = g * 256 + u;
    float v = Wh[k * Z4 + oc];
    __nv_bfloat16 hi = __float2bfloat16(v);
    __nv_bfloat16 lo = __float2bfloat16(v - __bfloat162float(hi));
    int kc = k >> 5, kk = k & 31;
    int e = (nt * 8 + kc) * TILE_E + loc * (ROWB / 2) + kk;
    g_bh[e] = hi;
    g_bl[e] = lo;
}

__global__ void prep_wxb(const float* __restrict__ Wx, const float* __restrict__ b) {
    int p = threadIdx.x;                        // 0..1023
    int nt = p >> 7, loc = p & 127;
    int wn = loc >> 6, g = (loc >> 4) & 3, ul = loc & 15;
    int oc = g * 256 + (nt * 32 + wn * 16 + ul);
    g_bp[p] = b[oc];
    #pragma unroll
    for (int f = 0; f < FDIM; f++)
        g_wxp[f * Z4 + p] = Wx[f * Z4 + oc];
}

// ---------------- main timestep kernel ----------------
__global__ void __launch_bounds__(THREADS)
lstm_step_mma(const float* __restrict__ xt, int xstride,
              const __nv_bfloat16* __restrict__ a_in_h,
              const __nv_bfloat16* __restrict__ a_in_l,
              __nv_bfloat16* __restrict__ a_out_h,
              __nv_bfloat16* __restrict__ a_out_l,
              int first)
{
    extern __shared__ char smem[];
    const uint32_t sb = (uint32_t)__cvta_generic_to_shared(smem);
    const int tid  = threadIdx.x;
    const int lane = tid & 31;
    const int wid  = tid >> 5;
    const int wm   = wid & 3;        // m-warp (rows wm*32..+32)
    const int wn   = wid >> 2;       // n-warp (cols wn*64..+64)
    const int nt = blockIdx.x;       // unit tile (0..7): units nt*32..+32
    const int rt = blockIdx.y;       // row tile (0..127)
    const int rbase = rt * 128;

    // permuted Wx / bias slices for this nt
    float* wx_s = (float*)(smem + SMEM_WX);     // [4][128]
    float* bp_s = (float*)(smem + SMEM_BIAS);   // [128]
    for (int i = tid; i < 4 * 128; i += THREADS) {
        int f = i >> 7, j = i & 127;
        wx_s[i] = g_wxp[f * Z4 + nt * 128 + j];
    }
    if (tid < 128) bp_s[tid] = g_bp[nt * 128 + tid];
    __syncthreads();

    float d[2][8][4];
    #pragma unroll
    for (int mi = 0; mi < 2; mi++)
        #pragma unroll
        for (int ni = 0; ni < 8; ni++)
            #pragma unroll
            for (int r = 0; r < 4; r++)
                d[mi][ni][r] = 0.0f;

    if (!first) {
        // ---- K loop: 8 chunks of 32, double-buffered cp.async ----
        // issue chunk c into stage c&1
        auto issue = [&](int c) {
            const uint32_t st = sb + (uint32_t)((c & 1) * STAGE_B);
            const __nv_bfloat16* srcs[4] = {
                a_in_h + (rt * 8 + c) * TILE_E,
                a_in_l + (rt * 8 + c) * TILE_E,
                g_bh   + (nt * 8 + c) * TILE_E,
                g_bl   + (nt * 8 + c) * TILE_E };
            #pragma unroll
            for (int t4 = 0; t4 < 4; t4++) {
                const char* s = (const char*)srcs[t4];
                for (int i = tid; i < TILE_B / 16; i += THREADS)
                    cp16(st + t4 * TILE_B + i * 16, s + i * 16);
            }
        };

        issue(0);
        asm volatile("cp.async.commit_group;" ::: "memory");

        for (int c = 0; c < 8; c++) {
            if (c < 7) {
                issue(c + 1);
                asm volatile("cp.async.commit_group;" ::: "memory");
                asm volatile("cp.async.wait_group 1;" ::: "memory");
            } else {
                asm volatile("cp.async.wait_group 0;" ::: "memory");
            }
            __syncthreads();

            const uint32_t st = sb + (uint32_t)((c & 1) * STAGE_B);
            #pragma unroll
            for (int k16 = 0; k16 < 2; k16++) {
                // A fragments (hi/lo), 2 m-tiles
                uint32_t ah[2][4], al[2][4];
                const int arow = wm * 32 + (lane & 7) + ((lane & 8) ? 8 : 0);
                const int akb  = k16 * 32 + ((lane & 16) ? 16 : 0);
                #pragma unroll
                for (int mi = 0; mi < 2; mi++) {
                    uint32_t ad = st + (uint32_t)((arow + mi * 16) * ROWB + akb);
                    ldsm4(ah[mi], ad);
                    ldsm4(al[mi], ad + TILE_B);
                }
                // B fragments (hi/lo), 8 n-tiles
                uint32_t bh[8][2], bl[8][2];
                const int bln = lane & 7;
                const int bkb = k16 * 32 + ((lane & 8) ? 16 : 0);
                #pragma unroll
                for (int ni = 0; ni < 8; ni++) {
                    uint32_t ad = st + (uint32_t)(2 * TILE_B +
                        (wn * 64 + ni * 8 + bln) * ROWB + bkb);
                    ldsm2(bh[ni], ad);
                    ldsm2(bl[ni], ad + TILE_B);
                }
                // 3-term MMAs
                #pragma unroll
                for (int mi = 0; mi < 2; mi++)
                    #pragma unroll
                    for (int ni = 0; ni < 8; ni++) {
                        mma16816(d[mi][ni], ah[mi], bh[ni]);
                        mma16816(d[mi][ni], al[mi], bh[ni]);
                        mma16816(d[mi][ni], ah[mi], bl[ni]);
                    }
            }
            __syncthreads();
        }
    }

    // ---- epilogue: z -> gates -> c,h; write fp32 h + bf16 hi/lo A tiles ----
    const int q = lane >> 2;        // row group within m8
    const int s4 = lane & 3;        // col group
    #pragma unroll
    for (int mi = 0; mi < 2; mi++) {
        #pragma unroll
        for (int rh = 0; rh < 2; rh++) {
            const int row = rbase + wm * 32 + mi * 16 + q + rh * 8;
            const float4 xv = *reinterpret_cast<const float4*>(
                &xt[(long)row * xstride]);
            #pragma unroll
            for (int sub = 0; sub < 2; sub++) {
                float hn2[2], ln2[2];
                #pragma unroll
                for (int par = 0; par < 2; par++) {
                    const int ul16 = sub * 8 + s4 * 2 + par;
                    const int u = nt * 32 + wn * 16 + ul16;
                    const int ci = row * NU + u;
                    const float cold = first ? 0.0f : g_c[ci];
                    float z[4];
                    #pragma unroll
                    for (int g = 0; g < 4; g++) {
                        const int nl = wn * 64 + g * 16 + ul16;
                        float zz = bp_s[nl] + d[mi][g * 2 + sub][rh * 2 + par];
                        zz = fmaf(xv.x, wx_s[nl],       zz);
                        zz = fmaf(xv.y, wx_s[128 + nl], zz);
                        zz = fmaf(xv.z, wx_s[256 + nl], zz);
                        zz = fmaf(xv.w, wx_s[384 + nl], zz);
                        z[g] = zz;
                    }
                    const float ig = sigmoid_acc(z[0]);
                    const float fg = sigmoid_acc(z[1]);
                    const float gg = tanhf(z[2]);
                    const float og = sigmoid_acc(z[3]);
                    const float cn = fg * cold + ig * gg;
                    const float hn = og * tanhf(cn);
                    g_c[ci] = cn;
                    g_h[ci] = hn;
                    hn2[par] = hn;
                    ln2[par] = 0.0f;  // placeholder
                }
                // pack bf16 hi/lo pairs and store into next-step A layout
                const int kk = wn * 16 + sub * 8 + s4 * 2;   // even
                const long eb = (long)(rt * 8 + nt) * TILE_E +
                                (row & 127) * (ROWB / 2) + kk;
                __nv_bfloat16 h0 = __float2bfloat16(hn2[0]);
                __nv_bfloat16 h1 = __float2bfloat16(hn2[1]);
                __nv_bfloat16 l0 = __float2bfloat16(hn2[0] - __bfloat162float(h0));
                __nv_bfloat16 l1 = __float2bfloat16(hn2[1] - __bfloat162float(h1));
                uint32_t ph = (uint32_t)__bfloat16_as_ushort(h0) |
                              ((uint32_t)__bfloat16_as_ushort(h1) << 16);
                uint32_t pl = (uint32_t)__bfloat16_as_ushort(l0) |
                              ((uint32_t)__bfloat16_as_ushort(l1) << 16);
                *reinterpret_cast<uint32_t*>(&a_out_h[eb]) = ph;
                *reinterpret_cast<uint32_t*>(&a_out_l[eb]) = pl;
                (void)ln2;
            }
        }
    }
}

// pred = h @ Wd + bd ; writes output slice and feedback buffer.
__global__ void pred_kernel(const float* __restrict__ h,
                            const float* __restrict__ Wd,
                            const float* __restrict__ bd,
                            float* __restrict__ out, int ostride,
                            float* __restrict__ pred)
{
    const int gwarp = (blockIdx.x * blockDim.x + threadIdx.x) >> 5;
    const int lane  = threadIdx.x & 31;
    if (gwarp >= BATCH) return;

    const float* hrow = h + gwarp * NU;
    float a0 = 0.f, a1 = 0.f, a2 = 0.f, a3 = 0.f;
    #pragma unroll
    for (int k = lane; k < NU; k += 32) {
        float hv = hrow[k];
        float4 wv = *reinterpret_cast<const float4*>(&Wd[k * 4]);
        a0 = fmaf(hv, wv.x, a0);
        a1 = fmaf(hv, wv.y, a1);
        a2 = fmaf(hv, wv.z, a2);
        a3 = fmaf(hv, wv.w, a3);
    }
    #pragma unroll
    for (int off = 16; off > 0; off >>= 1) {
        a0 += __shfl_down_sync(0xffffffffu, a0, off);
        a1 += __shfl_down_sync(0xffffffffu, a1, off);
        a2 += __shfl_down_sync(0xffffffffu, a2, off);
        a3 += __shfl_down_sync(0xffffffffu, a3, off);
    }
    if (lane == 0) {
        float4 r = make_float4(a0 + bd[0], a1 + bd[1], a2 + bd[2], a3 + bd[3]);
        *reinterpret_cast<float4*>(&out[(long)gwarp * ostride]) = r;
        *reinterpret_cast<float4*>(&pred[gwarp * 4]) = r;
    }
}

extern "C" void kernel_launch(void* const* d_in, const int* in_sizes, int n_in,
                              void* d_out, int out_size)
{
    const float* x  = (const float*)d_in[0];
    const float* Wx = (const float*)d_in[1];
    const float* Wh = (const float*)d_in[2];
    const float* b  = (const float*)d_in[3];
    const float* Wd = (const float*)d_in[4];
    const float* bd = (const float*)d_in[5];
    float* out = (float*)d_out;

    cudaFuncSetAttribute(lstm_step_mma,
                         cudaFuncAttributeMaxDynamicSharedMemorySize, SMEM_TOTAL);

    float* pred_ptr = nullptr;
    float* h_ptr = nullptr;
    __nv_bfloat16* ah = nullptr;
    __nv_bfloat16* al = nullptr;
    cudaGetSymbolAddress((void**)&pred_ptr, g_pred);
    cudaGetSymbolAddress((void**)&h_ptr, g_h);
    cudaGetSymbolAddress((void**)&ah, g_ah);
    cudaGetSymbolAddress((void**)&al, g_al);
    const long BUFE = 128L * 8 * TILE_E;
    __nv_bfloat16* ahb[2] = {ah, ah + BUFE};
    __nv_bfloat16* alb[2] = {al, al + BUFE};

    // weight prep (re-run every replay -> deterministic)
    prep_weights<<<1024, 256>>>(Wh);
    prep_wxb<<<1, 1024>>>(Wx, b);

    const dim3 sgrid(8, 128);                 // (unit tiles, row tiles)
    const int pblocks = (BATCH * 32) / 256;

    int step = 0;
    // step 0: h=c=0 -> GEMM skipped, epilogue seeds state
    lstm_step_mma<<<sgrid, THREADS, SMEM_TOTAL>>>(x, SEQ_T * FDIM,
        ahb[1], alb[1], ahb[0], alb[0], 1);
    step = 1;
    for (int t = 1; t < SEQ_T; t++, step++)
        lstm_step_mma<<<sgrid, THREADS, SMEM_TOTAL>>>(x + t * FDIM, SEQ_T * FDIM,
            ahb[(step - 1) & 1], alb[(step - 1) & 1],
            ahb[step & 1], alb[step & 1], 0);

    pred_kernel<<<pblocks, 256>>>(h_ptr, Wd, bd, out, NOUT * FDIM, pred_ptr);

    for (int s = 1; s < NOUT; s++, step++) {
        lstm_step_mma<<<sgrid, THREADS, SMEM_TOTAL>>>(pred_ptr, FDIM,
            ahb[(step - 1) & 1], alb[(step - 1) & 1],
            ahb[step & 1], alb[step & 1], 0);
        pred_kernel<<<pblocks, 256>>>(h_ptr, Wd, bd, out + s * FDIM,
                                      NOUT * FDIM, pred_ptr);
    }
}